// round 1
// baseline (speedup 1.0000x reference)
#include <cuda_runtime.h>
#include <math.h>

#define B_  2
#define H_  64
#define W_  64
#define HW_ 4096
#define N_  8192        // B*HW
#define C1_ 768
#define C2_ 256
#define M_  256

// ---------------- scratch (static device globals; no allocation) ----------------
__device__ __align__(16) float g_hcat[B_*C1_*HW_];   // 25 MB concat input
__device__ __align__(16) float g_om  [B_*27*HW_];    // offset-conv output (reused pass2)
__device__ __align__(16) float g_val [C1_*9*N_];     // 226 MB deformed im2col (reused pass2)
__device__ __align__(16) float g_acc [B_*M_*HW_];    // GEMM accumulator (pre-BN)
__device__ __align__(16) float g_h1  [B_*M_*HW_];    // after BN1+ReLU
__device__ __align__(16) float g_h2  [B_*M_*HW_];    // after BN2+ReLU

// ---------------- concat [x, msg1, msg2] along channels ----------------
__global__ void k_concat(const float* __restrict__ x, const float* __restrict__ m1,
                         const float* __restrict__ m2) {
    int i = blockIdx.x * 256 + threadIdx.x;
    if (i >= B_*C2_*HW_) return;
    int b = i / (C2_*HW_);
    int r = i - b * (C2_*HW_);
    float* d = g_hcat + b * C1_ * HW_;
    d[r]              = x[i];
    d[C2_*HW_ + r]    = m1[i];
    d[2*C2_*HW_ + r]  = m2[i];
}

// ---------------- init g_om with conv bias (accumulation target) ----------------
__global__ void k_initom(const float* __restrict__ bias) {
    int i = blockIdx.x * 256 + threadIdx.x;
    if (i >= B_*27*HW_) return;
    g_om[i] = bias[(i >> 12) % 27];
}

// ---------------- direct 3x3 conv, 27 out channels (offset/mask conv) ----------------
// grid: (B*H, CIN/32), block: 32 threads. Thread covers pixels (h,w) and (h,w+32),
// accumulates 27 output channels over a 32-channel input chunk, atomicAdds into g_om.
template<int CIN, int SRC>
__global__ void k_offconv(const float* __restrict__ wgt) {
    const float* img = (SRC == 0) ? g_hcat : g_h1;
    int bh = blockIdx.x;              // 0..127
    int b  = bh >> 6, h = bh & 63;
    int w0 = threadIdx.x;             // 0..31
    int cbase = blockIdx.y * 32;

    float a0[27], a1[27];
#pragma unroll
    for (int i = 0; i < 27; i++) { a0[i] = 0.f; a1[i] = 0.f; }

    for (int cc = 0; cc < 32; cc++) {
        int c = cbase + cc;
        const float* ip = img + (size_t)(b*CIN + c) * HW_;
        float x0[9], x1[9];
#pragma unroll
        for (int ky = 0; ky < 3; ky++) {
            int y = h + ky - 1;
            bool yok = ((unsigned)y < 64u);
#pragma unroll
            for (int kx = 0; kx < 3; kx++) {
                int xa = w0 + kx - 1;
                int xb = w0 + 32 + kx - 1;
                x0[ky*3+kx] = (yok && (unsigned)xa < 64u) ? ip[y*64 + xa] : 0.f;
                x1[ky*3+kx] = (yok && (unsigned)xb < 64u) ? ip[y*64 + xb] : 0.f;
            }
        }
        const float* wp = wgt + c * 9;
#pragma unroll
        for (int oc = 0; oc < 27; oc++) {
            const float* wo = wp + oc * CIN * 9;
#pragma unroll
            for (int k = 0; k < 9; k++) {
                float wv = __ldg(wo + k);
                a0[oc] += x0[k] * wv;
                a1[oc] += x1[k] * wv;
            }
        }
    }
    int hwp = h * 64 + w0;
#pragma unroll
    for (int oc = 0; oc < 27; oc++) {
        atomicAdd(&g_om[(b*27 + oc)*HW_ + hwp],      a0[oc]);
        atomicAdd(&g_om[(b*27 + oc)*HW_ + hwp + 32], a1[oc]);
    }
}

// ---------------- deformable bilinear sampling -> im2col matrix g_val[K, N] ----------------
// grid: (N/128, 9), block: 128. One thread per (b,hw) for a fixed tap k; loops channels.
template<int CIN, int SRC>
__global__ void k_sample() {
    int pos = blockIdx.x * 128 + threadIdx.x;   // b*HW + hw
    int k   = blockIdx.y;
    int b   = pos >> 12, hw = pos & 4095;
    int h   = hw >> 6,  w  = hw & 63;

    const float* om = g_om + b * 27 * HW_;
    float dy = om[(2*k  )*HW_ + hw];
    float dx = om[(2*k+1)*HW_ + hw];
    float mk = om[(18+k )*HW_ + hw];
    mk = 1.f / (1.f + expf(-mk));

    float ys = dy + (float)h + (float)(k / 3 - 1);
    float xs = dx + (float)w + (float)(k % 3 - 1);
    float y0f = floorf(ys), x0f = floorf(xs);
    float wy = ys - y0f, wx = xs - x0f;
    int y0 = (int)y0f, x0 = (int)x0f;
    int y1 = y0 + 1,   x1 = x0 + 1;

    bool v00 = ((unsigned)y0 < 64u) && ((unsigned)x0 < 64u);
    bool v01 = ((unsigned)y0 < 64u) && ((unsigned)x1 < 64u);
    bool v10 = ((unsigned)y1 < 64u) && ((unsigned)x0 < 64u);
    bool v11 = ((unsigned)y1 < 64u) && ((unsigned)x1 < 64u);

    float w00 = (1.f-wy)*(1.f-wx) * (v00 ? mk : 0.f);
    float w01 = (1.f-wy)*wx       * (v01 ? mk : 0.f);
    float w10 = wy*(1.f-wx)       * (v10 ? mk : 0.f);
    float w11 = wy*wx             * (v11 ? mk : 0.f);

    int cy0 = min(max(y0,0),63), cx0 = min(max(x0,0),63);
    int cy1 = min(max(y1,0),63), cx1 = min(max(x1,0),63);
    int i00 = cy0*64+cx0, i01 = cy0*64+cx1, i10 = cy1*64+cx0, i11 = cy1*64+cx1;

    const float* base = ((SRC == 0) ? g_hcat : g_h1) + (size_t)b * CIN * HW_;
    float* vp = g_val + k * N_ + pos;   // row (c*9+k), col pos
#pragma unroll 4
    for (int c = 0; c < CIN; c++) {
        const float* ip = base + c * HW_;
        float v = w00*__ldg(ip+i00) + w01*__ldg(ip+i01)
                + w10*__ldg(ip+i10) + w11*__ldg(ip+i11);
        vp[c * 9 * N_] = v;
    }
}

// ---------------- zero accumulator ----------------
__global__ void k_zero() {
    int i = blockIdx.x * 256 + threadIdx.x;
    if (i < B_*M_*HW_) g_acc[i] = 0.f;
}

// ---------------- SGEMM: C[256, 8192] += W[256, KDIM] * g_val[KDIM, 8192] ----------------
// BM=128, BN=128, BK=8, 256 threads, 8x8 per thread. K-split over gridDim.z, atomicAdd
// partials into g_acc (layout [b][o][hw]).
#define BM 128
#define BN 128
#define BK 8
template<int KDIM>
__global__ void __launch_bounds__(256) k_gemm(const float* __restrict__ A) {
    __shared__ float As[BK][BM];
    __shared__ float Bs[BK][BN];
    const int klen   = KDIM / gridDim.z;
    const int kstart = blockIdx.z * klen;
    int tid = threadIdx.x;
    int bm = blockIdx.y * BM;
    int bn = blockIdx.x * BN;
    int arow = tid >> 1,  acol = (tid & 1) * 4;
    int brow = tid >> 5,  bcol = (tid & 31) * 4;
    int tr = (tid >> 4) << 3, tc = (tid & 15) << 3;

    float acc[8][8];
#pragma unroll
    for (int i = 0; i < 8; i++)
#pragma unroll
        for (int j = 0; j < 8; j++) acc[i][j] = 0.f;

    const float* Ap = A + (size_t)(bm + arow) * KDIM + kstart + acol;
    const float* Bp = g_val + (size_t)(kstart + brow) * N_ + bn + bcol;

    for (int k0 = 0; k0 < klen; k0 += BK) {
        float4 av = *(const float4*)Ap;
        float4 bv = *(const float4*)Bp;
        Ap += BK;
        Bp += (size_t)BK * N_;
        As[acol+0][arow] = av.x;
        As[acol+1][arow] = av.y;
        As[acol+2][arow] = av.z;
        As[acol+3][arow] = av.w;
        *(float4*)&Bs[brow][bcol] = bv;
        __syncthreads();
#pragma unroll
        for (int kk = 0; kk < BK; kk++) {
            float ar[8], br[8];
            *(float4*)(ar)   = *(const float4*)&As[kk][tr];
            *(float4*)(ar+4) = *(const float4*)&As[kk][tr+4];
            *(float4*)(br)   = *(const float4*)&Bs[kk][tc];
            *(float4*)(br+4) = *(const float4*)&Bs[kk][tc+4];
#pragma unroll
            for (int i = 0; i < 8; i++)
#pragma unroll
                for (int j = 0; j < 8; j++) acc[i][j] += ar[i] * br[j];
        }
        __syncthreads();
    }
#pragma unroll
    for (int i = 0; i < 8; i++) {
        int o = bm + tr + i;
#pragma unroll
        for (int j = 0; j < 8; j++) {
            int n = bn + tc + j;
            int nb = n >> 12, nhw = n & 4095;
            atomicAdd(&g_acc[(nb*M_ + o)*HW_ + nhw], acc[i][j]);
        }
    }
}

// ---------------- fused BN + ReLU ----------------
template<int SEL>
__global__ void k_bnrelu(const float* __restrict__ g, const float* __restrict__ bb,
                         const float* __restrict__ bm, const float* __restrict__ bv) {
    int i = blockIdx.x * 256 + threadIdx.x;
    if (i >= B_*M_*HW_) return;
    int o = (i >> 12) & 255;
    float sc = g[o] / sqrtf(bv[o] + 1e-5f);
    float sh = bb[o] - bm[o] * sc;
    float v = g_acc[i] * sc + sh;
    v = v > 0.f ? v : 0.f;
    ((SEL == 0) ? g_h1 : g_h2)[i] = v;
}

// ---------------- residual + leaky relu ----------------
__global__ void k_final(const float* __restrict__ x, const float* __restrict__ gamma,
                        float* __restrict__ out) {
    int i = blockIdx.x * 256 + threadIdx.x;
    if (i >= B_*M_*HW_) return;
    float v = x[i] + gamma[0] * g_h2[i];
    out[i] = (v >= 0.f) ? v : 0.01f * v;
}

// ---------------- launch ----------------
extern "C" void kernel_launch(void* const* d_in, const int* in_sizes, int n_in,
                              void* d_out, int out_size) {
    const float* x     = (const float*)d_in[0];
    const float* msg1  = (const float*)d_in[1];
    const float* msg2  = (const float*)d_in[2];
    const float* woff1 = (const float*)d_in[3];
    const float* boff1 = (const float*)d_in[4];
    const float* w1    = (const float*)d_in[5];
    const float* bn1g  = (const float*)d_in[6];
    const float* bn1b  = (const float*)d_in[7];
    const float* bn1m  = (const float*)d_in[8];
    const float* bn1v  = (const float*)d_in[9];
    const float* woff2 = (const float*)d_in[10];
    const float* boff2 = (const float*)d_in[11];
    const float* w2    = (const float*)d_in[12];
    const float* bn2g  = (const float*)d_in[13];
    const float* bn2b  = (const float*)d_in[14];
    const float* bn2m  = (const float*)d_in[15];
    const float* bn2v  = (const float*)d_in[16];
    const float* gamma = (const float*)d_in[17];
    float* out = (float*)d_out;

    const int elems = B_*M_*HW_;                 // 2,097,152

    // ---- pass 1 (Cin = 768) ----
    k_concat<<<(elems + 255)/256, 256>>>(x, msg1, msg2);
    k_initom<<<(B_*27*HW_ + 255)/256, 256>>>(boff1);
    k_offconv<C1_, 0><<<dim3(B_*H_, C1_/32), 32>>>(woff1);
    k_sample<C1_, 0><<<dim3(N_/128, 9), 128>>>();
    k_zero<<<(elems + 255)/256, 256>>>();
    k_gemm<C1_*9><<<dim3(N_/BN, M_/BM, 2), 256>>>(w1);
    k_bnrelu<0><<<(elems + 255)/256, 256>>>(bn1g, bn1b, bn1m, bn1v);

    // ---- pass 2 (Cin = 256) ----
    k_initom<<<(B_*27*HW_ + 255)/256, 256>>>(boff2);
    k_offconv<C2_, 1><<<dim3(B_*H_, C2_/32), 32>>>(woff2);
    k_sample<C2_, 1><<<dim3(N_/128, 9), 128>>>();
    k_zero<<<(elems + 255)/256, 256>>>();
    k_gemm<C2_*9><<<dim3(N_/BN, M_/BM, 2), 256>>>(w2);
    k_bnrelu<1><<<(elems + 255)/256, 256>>>(bn2g, bn2b, bn2m, bn2v);

    // ---- residual + leaky ----
    k_final<<<(elems + 255)/256, 256>>>(x, gamma, out);
}

// round 5
// speedup vs baseline: 1.6361x; 1.6361x over previous
#include <cuda_runtime.h>
#include <cuda_bf16.h>
#include <cstdint>
#include <math.h>

#define B_  2
#define H_  64
#define W_  64
#define HW_ 4096
#define N_  8192        // B*HW
#define C1_ 768
#define C2_ 256
#define M_  256
#define K1_ (C1_*9)     // 6912
#define K2_ (C2_*9)     // 2304

// ---------------- scratch (static device globals; no allocation) ----------------
__device__ __align__(16) float g_hcat[B_*C1_*HW_];             // 25 MB concat input
__device__ __align__(16) float g_om  [B_*27*HW_];              // offset-conv output
__device__ __align__(16) __nv_bfloat16 g_valh[(size_t)N_*K1_]; // im2col hi (113MB)
__device__ __align__(16) __nv_bfloat16 g_vall[(size_t)N_*K1_]; // im2col lo
__device__ __align__(16) __nv_bfloat16 g_Ah[M_*K1_];           // weights hi (reordered)
__device__ __align__(16) __nv_bfloat16 g_Al[M_*K1_];           // weights lo
__device__ __align__(16) float g_h1[B_*M_*HW_];                // after BN1+ReLU

// ---------------- concat [x, msg1, msg2] ----------------
__global__ void k_concat(const float* __restrict__ x, const float* __restrict__ m1,
                         const float* __restrict__ m2) {
    int i = blockIdx.x * 256 + threadIdx.x;
    if (i >= B_*C2_*HW_) return;
    int b = i / (C2_*HW_);
    int r = i - b * (C2_*HW_);
    float* d = g_hcat + (size_t)b * C1_ * HW_;
    d[r]              = x[i];
    d[C2_*HW_ + r]    = m1[i];
    d[2*C2_*HW_ + r]  = m2[i];
}

// ---------------- init g_om with conv bias ----------------
__global__ void k_initom(const float* __restrict__ bias) {
    int i = blockIdx.x * 256 + threadIdx.x;
    if (i >= B_*27*HW_) return;
    g_om[i] = bias[(i >> 12) % 27];
}

// ---------------- direct 3x3 conv, 27 out channels (offset/mask conv) ----------------
// 128 threads = 4 rows x 32 lanes. Thread covers pixels (h,w) and (h,w+32).
template<int CIN, int SRC>
__global__ void __launch_bounds__(128) k_offconv(const float* __restrict__ wgt) {
    const float* img = (SRC == 0) ? g_hcat : g_h1;
    int bh = blockIdx.x * 4 + (threadIdx.x >> 5);   // 0..127
    int b  = bh >> 6, h = bh & 63;
    int w0 = threadIdx.x & 31;
    int cbase = blockIdx.y * 32;

    float a0[27], a1[27];
#pragma unroll
    for (int i = 0; i < 27; i++) { a0[i] = 0.f; a1[i] = 0.f; }

    for (int cc = 0; cc < 32; cc++) {
        int c = cbase + cc;
        const float* ip = img + (size_t)(b*CIN + c) * HW_;
        float x0[9], x1[9];
#pragma unroll
        for (int ky = 0; ky < 3; ky++) {
            int y = h + ky - 1;
            bool yok = ((unsigned)y < 64u);
#pragma unroll
            for (int kx = 0; kx < 3; kx++) {
                int xa = w0 + kx - 1;
                int xb = w0 + 32 + kx - 1;
                x0[ky*3+kx] = (yok && (unsigned)xa < 64u) ? ip[y*64 + xa] : 0.f;
                x1[ky*3+kx] = (yok && (unsigned)xb < 64u) ? ip[y*64 + xb] : 0.f;
            }
        }
        const float* wp = wgt + c * 9;
#pragma unroll
        for (int oc = 0; oc < 27; oc++) {
            const float* wo = wp + oc * CIN * 9;
#pragma unroll
            for (int k = 0; k < 9; k++) {
                float wv = __ldg(wo + k);
                a0[oc] += x0[k] * wv;
                a1[oc] += x1[k] * wv;
            }
        }
    }
    int hwp = h * 64 + w0;
#pragma unroll
    for (int oc = 0; oc < 27; oc++) {
        atomicAdd(&g_om[(b*27 + oc)*HW_ + hwp],      a0[oc]);
        atomicAdd(&g_om[(b*27 + oc)*HW_ + hwp + 32], a1[oc]);
    }
}

// ---------------- deformable bilinear sampling -> bf16 hi/lo im2col [N][K] ----------------
template<int CIN, int SRC>
__global__ void k_sample() {
    constexpr int K = CIN * 9;
    int pos = blockIdx.x * 128 + threadIdx.x;  // b*HW + hw
    int kk  = blockIdx.y;
    int b   = pos >> 12, hw = pos & 4095;
    int h   = hw >> 6,  w  = hw & 63;

    const float* om = g_om + (size_t)b * 27 * HW_;
    float dy = om[(2*kk  )*HW_ + hw];
    float dx = om[(2*kk+1)*HW_ + hw];
    float mk = om[(18+kk )*HW_ + hw];
    mk = 1.f / (1.f + expf(-mk));

    float ys = dy + (float)h + (float)(kk / 3 - 1);
    float xs = dx + (float)w + (float)(kk % 3 - 1);
    float y0f = floorf(ys), x0f = floorf(xs);
    float wy = ys - y0f, wx = xs - x0f;
    int y0 = (int)y0f, x0 = (int)x0f;
    int y1 = y0 + 1,   x1 = x0 + 1;

    bool v00 = ((unsigned)y0 < 64u) && ((unsigned)x0 < 64u);
    bool v01 = ((unsigned)y0 < 64u) && ((unsigned)x1 < 64u);
    bool v10 = ((unsigned)y1 < 64u) && ((unsigned)x0 < 64u);
    bool v11 = ((unsigned)y1 < 64u) && ((unsigned)x1 < 64u);

    float w00 = (1.f-wy)*(1.f-wx) * (v00 ? mk : 0.f);
    float w01 = (1.f-wy)*wx       * (v01 ? mk : 0.f);
    float w10 = wy*(1.f-wx)       * (v10 ? mk : 0.f);
    float w11 = wy*wx             * (v11 ? mk : 0.f);

    int cy0 = min(max(y0,0),63), cx0 = min(max(x0,0),63);
    int cy1 = min(max(y1,0),63), cx1 = min(max(x1,0),63);
    int i00 = cy0*64+cx0, i01 = cy0*64+cx1, i10 = cy1*64+cx0, i11 = cy1*64+cx1;

    int c0base = blockIdx.z * 256;
    const float* base = ((SRC == 0) ? g_hcat : g_h1) + (size_t)b * CIN * HW_
                      + (size_t)c0base * HW_;
    __nv_bfloat16* oh = g_valh + (size_t)pos * K + kk*CIN + c0base;
    __nv_bfloat16* ol = g_vall + (size_t)pos * K + kk*CIN + c0base;

    for (int c0 = 0; c0 < 256; c0 += 8) {
        __align__(16) __nv_bfloat16 hb[8];
        __align__(16) __nv_bfloat16 lb[8];
#pragma unroll
        for (int i = 0; i < 8; i++) {
            const float* ip = base + (size_t)(c0 + i) * HW_;
            float v = w00*__ldg(ip+i00) + w01*__ldg(ip+i01)
                    + w10*__ldg(ip+i10) + w11*__ldg(ip+i11);
            __nv_bfloat16 hv = __float2bfloat16(v);
            hb[i] = hv;
            lb[i] = __float2bfloat16(v - __bfloat162float(hv));
        }
        *(uint4*)(oh + c0) = *(const uint4*)hb;
        *(uint4*)(ol + c0) = *(const uint4*)lb;
    }
}

// ---------------- weight prep: fp32 [M][CIN][9] -> bf16 hi/lo [M][K], K = kk*CIN+c ----------------
template<int CIN>
__global__ void k_prepA(const float* __restrict__ wsrc) {
    constexpr int K = CIN * 9;
    int t = blockIdx.x * 256 + threadIdx.x;
    if (t >= M_ * K) return;
    int o = t / K, r = t - o * K;
    int kk = r / CIN, c = r - kk * CIN;
    float v = wsrc[(o*CIN + c)*9 + kk];
    __nv_bfloat16 hv = __float2bfloat16(v);
    g_Ah[t] = hv;
    g_Al[t] = __float2bfloat16(v - __bfloat162float(hv));
}

// ================= mma.sync GEMM =================
// C[256,8192] = W[256,KD] * val[KD,8192]^T(stored [N][K]); bf16 hi/lo, 3 products.
// CTA 128x128, BK=32, 8 warps (2x4), warp tile 64x32, 3-stage cp.async pipeline.
// Smem per stage: Ah,Al,Bh,Bl each 128 rows x 40 halves (pad 32->40, conflict-free).
#define STAGES      3
#define TILE_HALVES (128*40)          // 5120 halves = 10240 bytes
#define STAGE_BYTES (4*TILE_HALVES*2) // 40960
#define GEMM_SMEM   (STAGES*STAGE_BYTES)

__device__ __forceinline__ void mma16816(float* d, const uint32_t* a, const uint32_t* b) {
    asm volatile(
        "mma.sync.aligned.m16n8k16.row.col.f32.bf16.bf16.f32 "
        "{%0,%1,%2,%3}, {%4,%5,%6,%7}, {%8,%9}, {%0,%1,%2,%3};"
        : "+f"(d[0]), "+f"(d[1]), "+f"(d[2]), "+f"(d[3])
        : "r"(a[0]), "r"(a[1]), "r"(a[2]), "r"(a[3]), "r"(b[0]), "r"(b[1]));
}

template<int KD>
__device__ __forceinline__ void fill_stage(char* sb, int bm, int bn, int k0) {
    int tid = threadIdx.x;
#pragma unroll
    for (int i = 0; i < 8; i++) {
        int id = tid + i * 256;            // 0..2047
        int tile = id >> 9;                // 0=Ah 1=Al 2=Bh 3=Bl
        int row  = (id >> 2) & 127;
        int c4   = id & 3;
        char* dstp = sb + tile * (TILE_HALVES*2) + row * 80 + c4 * 16;
        uint32_t dst;
        asm("{ .reg .u64 t; cvta.to.shared.u64 t, %1; cvt.u32.u64 %0, t; }" : "=r"(dst) : "l"(dstp));
        const __nv_bfloat16* src;
        if      (tile == 0) src = g_Ah   + (size_t)(bm + row) * KD + k0 + c4 * 8;
        else if (tile == 1) src = g_Al   + (size_t)(bm + row) * KD + k0 + c4 * 8;
        else if (tile == 2) src = g_valh + (size_t)(bn + row) * KD + k0 + c4 * 8;
        else                src = g_vall + (size_t)(bn + row) * KD + k0 + c4 * 8;
        asm volatile("cp.async.cg.shared.global [%0], [%1], 16;" :: "r"(dst), "l"(src));
    }
}

template<int KD, int SEL>
__global__ void __launch_bounds__(256, 1) k_mmagemm(
        const float* __restrict__ bg,  const float* __restrict__ bb,
        const float* __restrict__ bmn, const float* __restrict__ bv,
        const float* __restrict__ xres, const float* __restrict__ gamma,
        float* __restrict__ outp) {
    extern __shared__ __align__(16) char dsm[];
    const int tid  = threadIdx.x;
    const int lane = tid & 31, wid = tid >> 5;
    const int wm = (wid & 1) * 64;
    const int wn = (wid >> 1) * 32;
    const int bm = blockIdx.y * 128, bn = blockIdx.x * 128;
    constexpr int T = KD / 32;

    float acc[4][4][4];
#pragma unroll
    for (int a = 0; a < 4; a++)
#pragma unroll
        for (int b = 0; b < 4; b++)
#pragma unroll
            for (int c = 0; c < 4; c++) acc[a][b][c] = 0.f;

    fill_stage<KD>(dsm, bm, bn, 0);
    asm volatile("cp.async.commit_group;" ::: "memory");
    fill_stage<KD>(dsm + STAGE_BYTES, bm, bn, 32);
    asm volatile("cp.async.commit_group;" ::: "memory");

    const int lr = lane >> 2;          // 0..7
    const int lc = (lane & 3) * 2;     // 0,2,4,6

    for (int it = 0; it < T; it++) {
        char* sb = dsm + (it % STAGES) * STAGE_BYTES;
        asm volatile("cp.async.wait_group 1;" ::: "memory");
        __syncthreads();
        if (it + 2 < T)
            fill_stage<KD>(dsm + ((it + 2) % STAGES) * STAGE_BYTES, bm, bn, (it + 2) * 32);
        asm volatile("cp.async.commit_group;" ::: "memory");

        const char* pA = sb;                          // Ah
        const char* pB = sb + 2*(TILE_HALVES*2);      // Bh
#pragma unroll
        for (int kb = 0; kb < 32; kb += 16) {
            uint32_t ah[4][4], al[4][4], bhf[4][2], blf[4][2];
#pragma unroll
            for (int mi = 0; mi < 4; mi++) {
                const char* p = pA + ((wm + mi*16 + lr) * 40 + kb + lc) * 2;
                ah[mi][0] = *(const uint32_t*)(p);
                ah[mi][1] = *(const uint32_t*)(p + 640);   // +8 rows
                ah[mi][2] = *(const uint32_t*)(p + 16);    // +8 k
                ah[mi][3] = *(const uint32_t*)(p + 656);
                al[mi][0] = *(const uint32_t*)(p + TILE_HALVES*2);
                al[mi][1] = *(const uint32_t*)(p + TILE_HALVES*2 + 640);
                al[mi][2] = *(const uint32_t*)(p + TILE_HALVES*2 + 16);
                al[mi][3] = *(const uint32_t*)(p + TILE_HALVES*2 + 656);
            }
#pragma unroll
            for (int ni = 0; ni < 4; ni++) {
                const char* p = pB + ((wn + ni*8 + lr) * 40 + kb + lc) * 2;
                bhf[ni][0] = *(const uint32_t*)(p);
                bhf[ni][1] = *(const uint32_t*)(p + 16);
                blf[ni][0] = *(const uint32_t*)(p + TILE_HALVES*2);
                blf[ni][1] = *(const uint32_t*)(p + TILE_HALVES*2 + 16);
            }
#pragma unroll
            for (int mi = 0; mi < 4; mi++)
#pragma unroll
                for (int ni = 0; ni < 4; ni++) {
                    mma16816(acc[mi][ni], ah[mi], bhf[ni]);
                    mma16816(acc[mi][ni], al[mi], bhf[ni]);
                    mma16816(acc[mi][ni], ah[mi], blf[ni]);
                }
        }
    }

    // epilogue: BN + ReLU (+ residual + leaky for SEL==1)
    float g0 = SEL ? gamma[0] : 0.f;
#pragma unroll
    for (int mi = 0; mi < 4; mi++) {
#pragma unroll
        for (int hh = 0; hh < 2; hh++) {
            int o = bm + wm + mi*16 + lr + hh*8;
            float sc = bg[o] * rsqrtf(bv[o] + 1e-5f);
            float sh = bb[o] - bmn[o] * sc;
#pragma unroll
            for (int ni = 0; ni < 4; ni++) {
                int n = bn + wn + ni*8 + lc;
                int b = n >> 12, hw = n & 4095;
                size_t idx = (size_t)(b*M_ + o) * HW_ + hw;
                float v0 = fmaxf(acc[mi][ni][hh*2+0] * sc + sh, 0.f);
                float v1 = fmaxf(acc[mi][ni][hh*2+1] * sc + sh, 0.f);
                if (SEL) {
                    float r0 = xres[idx]   + g0 * v0;
                    float r1 = xres[idx+1] + g0 * v1;
                    r0 = (r0 >= 0.f) ? r0 : 0.01f * r0;
                    r1 = (r1 >= 0.f) ? r1 : 0.01f * r1;
                    *(float2*)(outp + idx) = make_float2(r0, r1);
                } else {
                    *(float2*)(g_h1 + idx) = make_float2(v0, v1);
                }
            }
        }
    }
}

// ---------------- launch ----------------
extern "C" void kernel_launch(void* const* d_in, const int* in_sizes, int n_in,
                              void* d_out, int out_size) {
    const float* x     = (const float*)d_in[0];
    const float* msg1  = (const float*)d_in[1];
    const float* msg2  = (const float*)d_in[2];
    const float* woff1 = (const float*)d_in[3];
    const float* boff1 = (const float*)d_in[4];
    const float* w1    = (const float*)d_in[5];
    const float* bn1g  = (const float*)d_in[6];
    const float* bn1b  = (const float*)d_in[7];
    const float* bn1m  = (const float*)d_in[8];
    const float* bn1v  = (const float*)d_in[9];
    const float* woff2 = (const float*)d_in[10];
    const float* boff2 = (const float*)d_in[11];
    const float* w2    = (const float*)d_in[12];
    const float* bn2g  = (const float*)d_in[13];
    const float* bn2b  = (const float*)d_in[14];
    const float* bn2m  = (const float*)d_in[15];
    const float* bn2v  = (const float*)d_in[16];
    const float* gamma = (const float*)d_in[17];
    float* out = (float*)d_out;

    static int s_attr_done = 0;
    if (!s_attr_done) {
        cudaFuncSetAttribute(k_mmagemm<K1_,0>, cudaFuncAttributeMaxDynamicSharedMemorySize, GEMM_SMEM);
        cudaFuncSetAttribute(k_mmagemm<K2_,1>, cudaFuncAttributeMaxDynamicSharedMemorySize, GEMM_SMEM);
        s_attr_done = 1;
    }

    const int elems = B_*M_*HW_;

    // ---- pass 1 (Cin = 768) ----
    k_concat<<<(elems + 255)/256, 256>>>(x, msg1, msg2);
    k_initom<<<(B_*27*HW_ + 255)/256, 256>>>(boff1);
    k_offconv<C1_, 0><<<dim3(B_*H_/4, C1_/32), 128>>>(woff1);
    k_prepA<C1_><<<(M_*K1_ + 255)/256, 256>>>(w1);
    k_sample<C1_, 0><<<dim3(N_/128, 9, C1_/256), 128>>>();
    k_mmagemm<K1_, 0><<<dim3(N_/128, M_/128), 256, GEMM_SMEM>>>(
        bn1g, bn1b, bn1m, bn1v, nullptr, nullptr, nullptr);

    // ---- pass 2 (Cin = 256) ----
    k_initom<<<(B_*27*HW_ + 255)/256, 256>>>(boff2);
    k_offconv<C2_, 1><<<dim3(B_*H_/4, C2_/32), 128>>>(woff2);
    k_prepA<C2_><<<(M_*K2_ + 255)/256, 256>>>(w2);
    k_sample<C2_, 1><<<dim3(N_/128, 9, C2_/256), 128>>>();
    k_mmagemm<K2_, 1><<<dim3(N_/128, M_/128), 256, GEMM_SMEM>>>(
        bn2g, bn2b, bn2m, bn2v, x, gamma, out);
}